// round 1
// baseline (speedup 1.0000x reference)
#include <cuda_runtime.h>

#define ALPHA 0.2f
#define EPS   1e-5f
#define BB    8
#define NN    2048
#define FF    128
#define PITCH 132   // 128 + 4 pad: float4-aligned, row-stride breaks phase-A conflicts

// Scratch (no allocation allowed): Wh [B,N,F], Wh1/Wh2 [B,N]
__device__ float g_Wh [BB * NN * FF];
__device__ float g_Wh1[BB * NN];
__device__ float g_Wh2[BB * NN];

// ---------------------------------------------------------------------------
// Kernel 1: Wh = h @ W^T + b ; Wh1 = Wh @ a[:128] ; Wh2 = Wh @ a[128:]
// 128 CTAs x 256 threads; W kept transposed in SMEM (conflict-free broadcast).
// ---------------------------------------------------------------------------
__global__ __launch_bounds__(256) void gat_k1(const float* __restrict__ h,
                                              const float* __restrict__ W,
                                              const float* __restrict__ bias,
                                              const float* __restrict__ aw) {
    extern __shared__ float sm1[];
    float* Wt   = sm1;            // [f][o]  (transposed W), 64 KB
    float* hrow = sm1 + FF * FF;  // [2][128]
    __shared__ float p1[8], p2[8];

    int tid = threadIdx.x;
    // Load W[o][f] -> Wt[f][o]
    for (int idx = tid; idx < FF * FF; idx += 256) {
        int o = idx >> 7, f = idx & 127;
        Wt[f * FF + o] = W[idx];
    }

    int o  = tid & 127;
    int rp = tid >> 7;           // 0/1: which of the 2 concurrent rows
    float bo = bias[o];
    float a1 = aw[o];
    float a2 = aw[FF + o];
    int row0 = blockIdx.x * 128; // 128 rows (flattened B*N) per CTA

    for (int rr = 0; rr < 128; rr += 2) {
        __syncthreads();                                  // Wt ready / prev hrow reads done
        hrow[tid] = h[(row0 + rr) * FF + tid];            // 2 rows, coalesced
        __syncthreads();

        float acc = bo;
        const float* hp = hrow + rp * FF;
        #pragma unroll 16
        for (int f = 0; f < FF; f++)
            acc = fmaf(hp[f], Wt[f * FF + o], acc);

        int row = row0 + rr + rp;
        g_Wh[row * FF + o] = acc;

        // Reduce acc*a1, acc*a2 over the 128 threads of this row (4 warps)
        float s1 = acc * a1, s2 = acc * a2;
        #pragma unroll
        for (int d = 16; d; d >>= 1) {
            s1 += __shfl_xor_sync(0xffffffffu, s1, d);
            s2 += __shfl_xor_sync(0xffffffffu, s2, d);
        }
        int w = tid >> 5;
        if ((tid & 31) == 0) { p1[w] = s1; p2[w] = s2; }
        __syncthreads();
        if (tid < 2) {
            int base = tid * 4;
            g_Wh1[row0 + rr + tid] = p1[base] + p1[base+1] + p1[base+2] + p1[base+3];
            g_Wh2[row0 + rr + tid] = p2[base] + p2[base+1] + p2[base+2] + p2[base+3];
        }
    }
}

// ---------------------------------------------------------------------------
// Kernel 2: fused  P = mask(exp(leaky(Wh1_i + Wh2_j)))  ->  H' = P@Wh / rowsum
//           -> LayerNorm -> leaky.  Grid = B*16 CTAs, each owns a 128-row
//           i-tile, streams 16 j-tiles.  256 threads, 8x8 outputs/thread.
//   thread (r = tid/16, c = tid%16) owns rows {r+16u}, cols {c+16k}
//   -> all SMEM reads in the matmul are broadcast / stride-1 (conflict-free).
// ---------------------------------------------------------------------------
__global__ __launch_bounds__(256) void gat_k2(const int* __restrict__ adj,
                                              float* __restrict__ out) {
    extern __shared__ float sm2[];
    float* Pt  = sm2;                // [j][PITCH] : P transposed (i inner)
    float* Whs = sm2 + 128 * PITCH;  // [j][PITCH] : Wh j-tile
    __shared__ float Wh1s[128], Wh2s[128], rs[128];

    int tid = threadIdx.x;
    int b   = blockIdx.x >> 4;
    int it  = blockIdx.x & 15;
    int r   = tid >> 4;   // 0..15
    int c   = tid & 15;   // 0..15

    if (tid < 128) Wh1s[tid] = g_Wh1[b * NN + it * 128 + tid];

    float acc[8][8];
    float rsum[8];
    #pragma unroll
    for (int u = 0; u < 8; u++) {
        rsum[u] = 0.f;
        #pragma unroll
        for (int k = 0; k < 8; k++) acc[u][k] = 0.f;
    }

    const int adjBase = (b * NN + it * 128) * NN;

    for (int jt = 0; jt < 16; jt++) {
        __syncthreads();   // prev tile's Pt/Whs reads done; Wh1s visible (jt=0)
        if (tid < 128) Wh2s[tid] = g_Wh2[b * NN + jt * 128 + tid];

        // Copy Wh j-tile (128x128 fp32) into SMEM, float4, coalesced
        const float4* Whg = (const float4*)(g_Wh + (b * NN + jt * 128) * FF);
        #pragma unroll
        for (int e = 0; e < 16; e++) {
            int idx = e * 256 + tid;        // 0..4095 float4s
            int j   = idx >> 5;
            int m   = idx & 31;
            float4 v = Whg[idx];
            *(float4*)(Whs + j * PITCH + 4 * m) = v;
        }
        __syncthreads();

        // Phase A: build P tile (transposed). adj reads coalesced over j.
        #pragma unroll 4
        for (int e = 0; e < 64; e++) {
            int i = 2 * e + (tid >> 7);
            int j = tid & 127;
            int av = adj[adjBase + i * NN + jt * 128 + j];
            float s = Wh1s[i] + Wh2s[j];
            s = (s >= 0.f) ? s : ALPHA * s;
            float p = av ? __expf(s) : 0.f;   // masked == exp(-9e15) == 0
            Pt[j * PITCH + i] = p;
        }
        __syncthreads();

        // Phase B: acc += P_tile @ Wh_tile  (register-tiled)
        #pragma unroll 2
        for (int j = 0; j < 128; j++) {
            float pv[8], wv[8];
            #pragma unroll
            for (int u = 0; u < 8; u++) pv[u] = Pt[j * PITCH + r + 16 * u];
            #pragma unroll
            for (int k = 0; k < 8; k++) wv[k] = Whs[j * PITCH + c + 16 * k];
            #pragma unroll
            for (int u = 0; u < 8; u++) {
                rsum[u] += pv[u];
                #pragma unroll
                for (int k = 0; k < 8; k++)
                    acc[u][k] = fmaf(pv[u], wv[k], acc[u][k]);
            }
        }
    }

    // rowsums: identical across c; publish from c==0
    __syncthreads();
    if (c == 0) {
        #pragma unroll
        for (int u = 0; u < 8; u++) rs[r + 16 * u] = rsum[u];
    }
    __syncthreads();

    // Epilogue: softmax-normalize, LayerNorm over F, leaky, store
    #pragma unroll
    for (int u = 0; u < 8; u++) {
        int i = r + 16 * u;
        float inv = 1.f / rs[i];
        float v[8];
        float s = 0.f, sq = 0.f;
        #pragma unroll
        for (int k = 0; k < 8; k++) {
            v[k] = acc[u][k] * inv;
            s   += v[k];
            sq   = fmaf(v[k], v[k], sq);
        }
        // reduce over the 16 lanes (same r, c=0..15) = one half-warp
        #pragma unroll
        for (int d = 1; d < 16; d <<= 1) {
            s  += __shfl_xor_sync(0xffffffffu, s,  d);
            sq += __shfl_xor_sync(0xffffffffu, sq, d);
        }
        float mu   = s * (1.f / 128.f);
        float var  = sq * (1.f / 128.f) - mu * mu;   // biased var (matches jnp.var)
        float rstd = rsqrtf(var + EPS);
        float* op  = out + (size_t)(b * NN + it * 128 + i) * FF;
        #pragma unroll
        for (int k = 0; k < 8; k++) {
            float y = (v[k] - mu) * rstd;
            y = (y >= 0.f) ? y : ALPHA * y;
            op[c + 16 * k] = y;
        }
    }
}

// ---------------------------------------------------------------------------
extern "C" void kernel_launch(void* const* d_in, const int* in_sizes, int n_in,
                              void* d_out, int out_size) {
    const float* h    = (const float*)d_in[0];
    const int*   adj  = (const int*)  d_in[1];
    const float* W    = (const float*)d_in[2];
    const float* bias = (const float*)d_in[3];
    const float* aw   = (const float*)d_in[4];
    float*       out  = (float*)d_out;

    const int smem1 = (FF * FF + 256) * (int)sizeof(float);      // 66.5 KB
    const int smem2 = 2 * 128 * PITCH * (int)sizeof(float);      // 132 KB

    cudaFuncSetAttribute(gat_k1, cudaFuncAttributeMaxDynamicSharedMemorySize, smem1);
    cudaFuncSetAttribute(gat_k2, cudaFuncAttributeMaxDynamicSharedMemorySize, smem2);

    gat_k1<<<128, 256, smem1>>>(h, W, bias, aw);
    gat_k2<<<BB * 16, 256, smem2>>>(adj, out);
}

// round 4
// speedup vs baseline: 1.6117x; 1.6117x over previous
#include <cuda_runtime.h>
#include <string.h>

#define ALPHA 0.2f
#define EPS   1e-5f
#define BB    8
#define NN    2048
#define FF    128
#define PD    258   // pitch (floats) of duplicated {v,v} arrays: 258%32==2 -> conflict-free paired reads
#define PS    132   // pitch (floats) of plain arrays

typedef unsigned long long ull;

// Scratch (no allocation allowed)
__device__ float g_Wh [BB * NN * FF];
__device__ float g_Wh1[BB * NN];
__device__ float g_Wh2[BB * NN];

__device__ __forceinline__ void fma2(ull& d, ull a, ull b) {
    asm("fma.rn.f32x2 %0, %1, %2, %0;" : "+l"(d) : "l"(a), "l"(b));
}
__device__ __forceinline__ float2 asf2(ull v) { float2 f; memcpy(&f, &v, 8); return f; }
__device__ __forceinline__ ull    asu2(float2 f) { ull v; memcpy(&v, &f, 8); return v; }

// ---------------------------------------------------------------------------
// Kernel 1: Wh = h @ W^T + b ; Wh1 = Wh@a[:128]; Wh2 = Wh@a[128:]
// FFMA2 register-tiled: CTA = 128 rows x 128 cols, K=128.
// hTd: h-tile transposed+duplicated [f][2i]; Wt: W transposed [f][o].
// thread (r=tid/16, c=tid%16): rows {r+16u}, col-pairs {2c+32k, +1}.
// ---------------------------------------------------------------------------
__global__ __launch_bounds__(256) void gat_k1(const float* __restrict__ h,
                                              const float* __restrict__ W,
                                              const float* __restrict__ bias,
                                              const float* __restrict__ aw) {
    extern __shared__ float sm[];
    float* hTd = sm;             // [128 f][PD]  (dup over i)
    float* Wt  = sm + 128 * PD;  // [128 f][PS]  (cols o)

    int tid = threadIdx.x;
    int r = tid >> 4, c = tid & 15;
    int row0 = blockIdx.x * 128;

    // Wt[f][o] <- W[o][f]
    for (int idx = tid; idx < FF * FF; idx += 256) {
        int o = idx >> 7, f = idx & 127;
        Wt[f * PS + o] = W[idx];
    }
    // hTd[f][2i] = hTd[f][2i+1] = h[row0+i][f]
    #pragma unroll
    for (int e = 0; e < 16; e++) {
        int idx = e * 256 + tid;
        int i = idx >> 5, m = idx & 31;          // f = 4m..4m+3
        float4 v = ((const float4*)(h + (size_t)(row0 + i) * FF))[m];
        float2 d;
        d.x = d.y = v.x; *(float2*)(hTd + (4*m+0) * PD + 2*i) = d;
        d.x = d.y = v.y; *(float2*)(hTd + (4*m+1) * PD + 2*i) = d;
        d.x = d.y = v.z; *(float2*)(hTd + (4*m+2) * PD + 2*i) = d;
        d.x = d.y = v.w; *(float2*)(hTd + (4*m+3) * PD + 2*i) = d;
    }
    __syncthreads();

    // acc init = bias pairs
    ull acc[8][4];
    #pragma unroll
    for (int k = 0; k < 4; k++) {
        float2 bp = *(const float2*)(bias + 2*c + 32*k);
        ull bu = asu2(bp);
        #pragma unroll
        for (int u = 0; u < 8; u++) acc[u][k] = bu;
    }

    const float* Bm = Wt + 2 * c;
    #pragma unroll 2
    for (int f = 0; f < 128; f++) {
        ull pv[8], wv[4];
        #pragma unroll
        for (int u = 0; u < 8; u++)
            pv[u] = *(const ull*)(hTd + f * PD + 2 * (r + 16 * u));
        #pragma unroll
        for (int k = 0; k < 4; k++)
            wv[k] = *(const ull*)(Bm + f * PS + 32 * k);
        #pragma unroll
        for (int u = 0; u < 8; u++)
            #pragma unroll
            for (int k = 0; k < 4; k++)
                fma2(acc[u][k], pv[u], wv[k]);
    }

    // a-vector pairs for Wh1/Wh2 partials
    float2 a1[4], a2[4];
    #pragma unroll
    for (int k = 0; k < 4; k++) {
        a1[k] = *(const float2*)(aw + 2*c + 32*k);
        a2[k] = *(const float2*)(aw + FF + 2*c + 32*k);
    }

    #pragma unroll
    for (int u = 0; u < 8; u++) {
        int row = row0 + r + 16 * u;
        float s1 = 0.f, s2 = 0.f;
        #pragma unroll
        for (int k = 0; k < 4; k++) {
            float2 v = asf2(acc[u][k]);
            *(float2*)(g_Wh + (size_t)row * FF + 2*c + 32*k) = v;
            s1 = fmaf(v.x, a1[k].x, fmaf(v.y, a1[k].y, s1));
            s2 = fmaf(v.x, a2[k].x, fmaf(v.y, a2[k].y, s2));
        }
        #pragma unroll
        for (int d = 1; d < 16; d <<= 1) {
            s1 += __shfl_xor_sync(0xffffffffu, s1, d);
            s2 += __shfl_xor_sync(0xffffffffu, s2, d);
        }
        if (c == 0) { g_Wh1[row] = s1; g_Wh2[row] = s2; }
    }
}

// ---------------------------------------------------------------------------
// Kernel 2: fused P=mask(exp(leaky(Wh1_i+Wh2_j))) -> H'=P@Wh/rowsum -> LN -> leaky
// Pd: P tile duplicated [i][2j] ({p,p} pairs); Whs: plain Wh j-tile [j][o].
// Phase B = FFMA2 register tile; rowsum via separate cheap pass.
// ---------------------------------------------------------------------------
__global__ __launch_bounds__(256) void gat_k2(const int* __restrict__ adj,
                                              float* __restrict__ out) {
    extern __shared__ float sm[];
    float* Pd  = sm;             // [128 i][PD]
    float* Whs = sm + 128 * PD;  // [128 j][PS]
    __shared__ float Wh1s[128];
    __shared__ float rsp[2][128];

    int tid  = threadIdx.x;
    int b    = blockIdx.x >> 4;
    int it   = blockIdx.x & 15;
    int r    = tid >> 4, c = tid & 15;
    int lane = tid & 31, w = tid >> 5;
    int iR   = tid & 127, hp = tid >> 7;

    if (tid < 128) Wh1s[tid] = g_Wh1[b * NN + it * 128 + tid];

    ull acc[8][4];
    #pragma unroll
    for (int u = 0; u < 8; u++)
        #pragma unroll
        for (int k = 0; k < 4; k++) acc[u][k] = 0ULL;
    float rsacc = 0.f;

    const int adjBase = (b * NN + it * 128) * NN;
    __syncthreads();   // Wh1s visible

    for (int jt = 0; jt < 16; jt++) {
        // ---- fill Whs (plain) ----
        const float4* Whg = (const float4*)(g_Wh + (size_t)(b * NN + jt * 128) * FF);
        #pragma unroll
        for (int e = 0; e < 16; e++) {
            int idx = e * 256 + tid;
            int j = idx >> 5, m = idx & 31;
            float4 v = Whg[idx];
            *(float4*)(Whs + j * PS + 4 * m) = v;
        }
        // Wh2 values for this tile (registers, coalesced LDG)
        float wh2q[4];
        #pragma unroll
        for (int q = 0; q < 4; q++)
            wh2q[q] = g_Wh2[b * NN + jt * 128 + lane + 32 * q];

        // ---- phase A: build Pd (adj coalesced, STS.64 conflict-free) ----
        #pragma unroll 4
        for (int s = 0; s < 16; s++) {
            int li = s * 8 + w;
            float wh1 = Wh1s[li];
            const int* ap = adj + adjBase + li * NN + jt * 128 + lane;
            #pragma unroll
            for (int q = 0; q < 4; q++) {
                int av = ap[32 * q];
                float sc = wh1 + wh2q[q];
                sc = (sc >= 0.f) ? sc : ALPHA * sc;
                float p = av ? __expf(sc) : 0.f;
                float2 pp; pp.x = p; pp.y = p;
                *(float2*)(Pd + li * PD + 2 * (lane + 32 * q)) = pp;
            }
        }
        __syncthreads();

        // ---- rowsum partials (per-thread register accumulation) ----
        {
            const float* pr = Pd + iR * PD + 2 * (hp * 64);
            float s0 = 0.f;
            #pragma unroll 16
            for (int jj = 0; jj < 64; jj++) s0 += pr[2 * jj];
            rsacc += s0;
        }

        // ---- phase B: acc += P @ Wh  (FFMA2) ----
        const float* Bm = Whs + 2 * c;
        #pragma unroll 2
        for (int j = 0; j < 128; j++) {
            ull pv[8], wv[4];
            #pragma unroll
            for (int u = 0; u < 8; u++)
                pv[u] = *(const ull*)(Pd + (r + 16 * u) * PD + 2 * j);
            #pragma unroll
            for (int k = 0; k < 4; k++)
                wv[k] = *(const ull*)(Bm + j * PS + 32 * k);
            #pragma unroll
            for (int u = 0; u < 8; u++)
                #pragma unroll
                for (int k = 0; k < 4; k++)
                    fma2(acc[u][k], pv[u], wv[k]);
        }
        __syncthreads();   // phase B / rowsum reads done before next tile overwrites
    }

    rsp[hp][iR] = rsacc;
    __syncthreads();

    // ---- epilogue: normalize, LayerNorm, leaky, store ----
    #pragma unroll
    for (int u = 0; u < 8; u++) {
        int i = r + 16 * u;
        float R   = rsp[0][i] + rsp[1][i];
        float inv = 1.f / R;
        float2 v[4];
        float s = 0.f, sq = 0.f;
        #pragma unroll
        for (int k = 0; k < 4; k++) {
            float2 a2v = asf2(acc[u][k]);
            v[k].x = a2v.x * inv; v[k].y = a2v.y * inv;
            s += v[k].x + v[k].y;
            sq = fmaf(v[k].x, v[k].x, fmaf(v[k].y, v[k].y, sq));
        }
        #pragma unroll
        for (int d = 1; d < 16; d <<= 1) {
            s  += __shfl_xor_sync(0xffffffffu, s,  d);
            sq += __shfl_xor_sync(0xffffffffu, sq, d);
        }
        float mu   = s * (1.f / 128.f);
        float var  = sq * (1.f / 128.f) - mu * mu;
        float rstd = rsqrtf(var + EPS);
        float* op = out + (size_t)(b * NN + it * 128 + i) * FF;
        #pragma unroll
        for (int k = 0; k < 4; k++) {
            float2 y;
            y.x = (v[k].x - mu) * rstd;
            y.y = (v[k].y - mu) * rstd;
            y.x = (y.x >= 0.f) ? y.x : ALPHA * y.x;
            y.y = (y.y >= 0.f) ? y.y : ALPHA * y.y;
            *(float2*)(op + 2 * c + 32 * k) = y;
        }
    }
}

// ---------------------------------------------------------------------------
extern "C" void kernel_launch(void* const* d_in, const int* in_sizes, int n_in,
                              void* d_out, int out_size) {
    const float* h    = (const float*)d_in[0];
    const int*   adj  = (const int*)  d_in[1];
    const float* W    = (const float*)d_in[2];
    const float* bias = (const float*)d_in[3];
    const float* aw   = (const float*)d_in[4];
    float*       out  = (float*)d_out;

    const int smem = (128 * PD + 128 * PS) * (int)sizeof(float);  // 199,680 B

    cudaFuncSetAttribute(gat_k1, cudaFuncAttributeMaxDynamicSharedMemorySize, smem);
    cudaFuncSetAttribute(gat_k2, cudaFuncAttributeMaxDynamicSharedMemorySize, smem);

    gat_k1<<<128, 256, smem>>>(h, W, bias, aw);
    gat_k2<<<BB * 16, 256, smem>>>(adj, out);
}

// round 6
// speedup vs baseline: 1.6840x; 1.0448x over previous
#include <cuda_runtime.h>
#include <string.h>

#define ALPHA 0.2f
#define EPS   1e-5f
#define BB    8
#define NN    2048
#define FF    128
#define PD    258   // dup-pitch (k1 only)
#define PS    132   // plain pitch

typedef unsigned long long ull;

// Scratch (no allocation allowed)
__device__ float g_Wh [BB * NN * FF];
__device__ float g_Wh1[BB * NN];
__device__ float g_Wh2[BB * NN];

__device__ __forceinline__ void fma2(ull& d, ull a, ull b) {
    asm("fma.rn.f32x2 %0, %1, %2, %0;" : "+l"(d) : "l"(a), "l"(b));
}
__device__ __forceinline__ ull splat2(float w) {
    ull d; asm("mov.b64 %0, {%1, %1};" : "=l"(d) : "f"(w)); return d;
}
__device__ __forceinline__ float2 asf2(ull v) { float2 f; memcpy(&f, &v, 8); return f; }
__device__ __forceinline__ ull    asu2(float2 f) { ull v; memcpy(&v, &f, 8); return v; }

// ---------------------------------------------------------------------------
// Kernel 1: Wh = h @ W^T + b ; Wh1 = Wh@a[:128]; Wh2 = Wh@a[128:]
// (unchanged — ~22 us, not the bottleneck)
// ---------------------------------------------------------------------------
__global__ __launch_bounds__(256) void gat_k1(const float* __restrict__ h,
                                              const float* __restrict__ W,
                                              const float* __restrict__ bias,
                                              const float* __restrict__ aw) {
    extern __shared__ float sm[];
    float* hTd = sm;             // [128 f][PD]  (dup over i)
    float* Wt  = sm + 128 * PD;  // [128 f][PS]  (cols o)

    int tid = threadIdx.x;
    int r = tid >> 4, c = tid & 15;
    int row0 = blockIdx.x * 128;

    for (int idx = tid; idx < FF * FF; idx += 256) {
        int o = idx >> 7, f = idx & 127;
        Wt[f * PS + o] = W[idx];
    }
    #pragma unroll
    for (int e = 0; e < 16; e++) {
        int idx = e * 256 + tid;
        int i = idx >> 5, m = idx & 31;
        float4 v = ((const float4*)(h + (size_t)(row0 + i) * FF))[m];
        float2 d;
        d.x = d.y = v.x; *(float2*)(hTd + (4*m+0) * PD + 2*i) = d;
        d.x = d.y = v.y; *(float2*)(hTd + (4*m+1) * PD + 2*i) = d;
        d.x = d.y = v.z; *(float2*)(hTd + (4*m+2) * PD + 2*i) = d;
        d.x = d.y = v.w; *(float2*)(hTd + (4*m+3) * PD + 2*i) = d;
    }
    __syncthreads();

    ull acc[8][4];
    #pragma unroll
    for (int k = 0; k < 4; k++) {
        float2 bp = *(const float2*)(bias + 2*c + 32*k);
        ull bu = asu2(bp);
        #pragma unroll
        for (int u = 0; u < 8; u++) acc[u][k] = bu;
    }

    const float* Bm = Wt + 2 * c;
    #pragma unroll 2
    for (int f = 0; f < 128; f++) {
        ull pv[8], wv[4];
        #pragma unroll
        for (int u = 0; u < 8; u++)
            pv[u] = *(const ull*)(hTd + f * PD + 2 * (r + 16 * u));
        #pragma unroll
        for (int k = 0; k < 4; k++)
            wv[k] = *(const ull*)(Bm + f * PS + 32 * k);
        #pragma unroll
        for (int u = 0; u < 8; u++)
            #pragma unroll
            for (int k = 0; k < 4; k++)
                fma2(acc[u][k], pv[u], wv[k]);
    }

    float2 a1[4], a2[4];
    #pragma unroll
    for (int k = 0; k < 4; k++) {
        a1[k] = *(const float2*)(aw + 2*c + 32*k);
        a2[k] = *(const float2*)(aw + FF + 2*c + 32*k);
    }

    #pragma unroll
    for (int u = 0; u < 8; u++) {
        int row = row0 + r + 16 * u;
        float s1 = 0.f, s2 = 0.f;
        #pragma unroll
        for (int k = 0; k < 4; k++) {
            float2 v = asf2(acc[u][k]);
            *(float2*)(g_Wh + (size_t)row * FF + 2*c + 32*k) = v;
            s1 = fmaf(v.x, a1[k].x, fmaf(v.y, a1[k].y, s1));
            s2 = fmaf(v.x, a2[k].x, fmaf(v.y, a2[k].y, s2));
        }
        #pragma unroll
        for (int d = 1; d < 16; d <<= 1) {
            s1 += __shfl_xor_sync(0xffffffffu, s1, d);
            s2 += __shfl_xor_sync(0xffffffffu, s2, d);
        }
        if (c == 0) { g_Wh1[row] = s1; g_Wh2[row] = s2; }
    }
}

// ---------------------------------------------------------------------------
// Kernel 2: fused GAT attention + aggregate + LN + leaky.
// Pt plain transposed [j][i] (pitch 132). FFMA2 pairs over ADJACENT i
// (natural LDS.64 from plain P); wv = {w,w} register splats.
// Crossbar bytes/thread/j: 96 -> 64 (removes the binding term).
// thread (r,c): row-pairs {2r+32u, +1} u=0..3, cols {c+16k} k=0..7.
// ---------------------------------------------------------------------------
__global__ __launch_bounds__(256) void gat_k2(const int* __restrict__ adj,
                                              float* __restrict__ out) {
    extern __shared__ float sm[];
    float* Pt  = sm;             // [128 j][PS] : P transposed, plain
    float* Whs = sm + 128 * PS;  // [128 j][PS] : Wh j-tile
    __shared__ float Wh1s[128];
    __shared__ float rsp[2][128];

    int tid  = threadIdx.x;
    int b    = blockIdx.x >> 4;
    int it   = blockIdx.x & 15;
    int r    = tid >> 4, c = tid & 15;
    int lane = tid & 31, w = tid >> 5;
    int iR   = tid & 127, hp = tid >> 7;

    if (tid < 128) Wh1s[tid] = g_Wh1[b * NN + it * 128 + tid];

    ull acc[4][8];
    #pragma unroll
    for (int u = 0; u < 4; u++)
        #pragma unroll
        for (int k = 0; k < 8; k++) acc[u][k] = 0ULL;
    float rsacc = 0.f;

    const int adjBase = (b * NN + it * 128) * NN;
    __syncthreads();   // Wh1s visible

    for (int jt = 0; jt < 16; jt++) {
        // ---- fill Whs ----
        const float4* Whg = (const float4*)(g_Wh + (size_t)(b * NN + jt * 128) * FF);
        #pragma unroll
        for (int e = 0; e < 16; e++) {
            int idx = e * 256 + tid;
            int j = idx >> 5, m = idx & 31;
            float4 v = Whg[idx];
            *(float4*)(Whs + j * PS + 4 * m) = v;
        }
        float wh2q[4];
        #pragma unroll
        for (int q = 0; q < 4; q++)
            wh2q[q] = g_Wh2[b * NN + jt * 128 + lane + 32 * q];

        // ---- phase A: build Pt (transposed: Pt[j][i]), scalar stores ----
        #pragma unroll 4
        for (int s = 0; s < 16; s++) {
            int li = s * 8 + w;                 // i index
            float wh1 = Wh1s[li];
            const int* ap = adj + adjBase + li * NN + jt * 128 + lane;
            #pragma unroll
            for (int q = 0; q < 4; q++) {
                int jj = lane + 32 * q;
                int av = ap[32 * q];
                float sc = wh1 + wh2q[q];
                sc = (sc >= 0.f) ? sc : ALPHA * sc;
                float p = av ? __expf(sc) : 0.f;
                Pt[jj * PS + li] = p;
            }
        }
        __syncthreads();

        // ---- rowsum partials (over j, per row iR) ----
        {
            const float* pr = Pt + hp * 64 * PS + iR;
            float s0 = 0.f;
            #pragma unroll 16
            for (int jj = 0; jj < 64; jj++) s0 += pr[jj * PS];
            rsacc += s0;
        }

        // ---- phase B: acc += P @ Wh  (FFMA2, i-paired) ----
        #pragma unroll 2
        for (int j = 0; j < 128; j++) {
            ull pv[4], wv[8];
            #pragma unroll
            for (int u = 0; u < 4; u++)
                pv[u] = *(const ull*)(Pt + j * PS + 2 * r + 32 * u);
            #pragma unroll
            for (int k = 0; k < 8; k++)
                wv[k] = splat2(Whs[j * PS + c + 16 * k]);
            #pragma unroll
            for (int u = 0; u < 4; u++)
                #pragma unroll
                for (int k = 0; k < 8; k++)
                    fma2(acc[u][k], pv[u], wv[k]);
        }
        __syncthreads();   // reads done before next tile overwrites
    }

    rsp[hp][iR] = rsacc;
    __syncthreads();

    // ---- epilogue: normalize, LayerNorm (per row-pair), leaky, store ----
    #pragma unroll
    for (int u = 0; u < 4; u++) {
        int i0 = 2 * r + 32 * u;
        float Rx = rsp[0][i0]     + rsp[1][i0];
        float Ry = rsp[0][i0 + 1] + rsp[1][i0 + 1];
        float2 inv; inv.x = 1.f / Rx; inv.y = 1.f / Ry;
        float2 v[8];
        float2 s;  s.x  = 0.f; s.y  = 0.f;
        float2 sq; sq.x = 0.f; sq.y = 0.f;
        #pragma unroll
        for (int k = 0; k < 8; k++) {
            float2 a2v = asf2(acc[u][k]);
            v[k].x = a2v.x * inv.x; v[k].y = a2v.y * inv.y;
            s.x += v[k].x;          s.y += v[k].y;
            sq.x = fmaf(v[k].x, v[k].x, sq.x);
            sq.y = fmaf(v[k].y, v[k].y, sq.y);
        }
        #pragma unroll
        for (int d = 1; d < 16; d <<= 1) {
            s.x  += __shfl_xor_sync(0xffffffffu, s.x,  d);
            s.y  += __shfl_xor_sync(0xffffffffu, s.y,  d);
            sq.x += __shfl_xor_sync(0xffffffffu, sq.x, d);
            sq.y += __shfl_xor_sync(0xffffffffu, sq.y, d);
        }
        float mux = s.x * (1.f / 128.f), muy = s.y * (1.f / 128.f);
        float rstdx = rsqrtf(sq.x * (1.f / 128.f) - mux * mux + EPS);
        float rstdy = rsqrtf(sq.y * (1.f / 128.f) - muy * muy + EPS);
        float* op0 = out + (size_t)(b * NN + it * 128 + i0) * FF;
        float* op1 = op0 + FF;
        #pragma unroll
        for (int k = 0; k < 8; k++) {
            float yx = (v[k].x - mux) * rstdx;
            float yy = (v[k].y - muy) * rstdy;
            yx = (yx >= 0.f) ? yx : ALPHA * yx;
            yy = (yy >= 0.f) ? yy : ALPHA * yy;
            op0[c + 16 * k] = yx;
            op1[c + 16 * k] = yy;
        }
    }
}

// ---------------------------------------------------------------------------
extern "C" void kernel_launch(void* const* d_in, const int* in_sizes, int n_in,
                              void* d_out, int out_size) {
    const float* h    = (const float*)d_in[0];
    const int*   adj  = (const int*)  d_in[1];
    const float* W    = (const float*)d_in[2];
    const float* bias = (const float*)d_in[3];
    const float* aw   = (const float*)d_in[4];
    float*       out  = (float*)d_out;

    const int smem1 = (128 * PD + 128 * PS) * (int)sizeof(float);  // 199,680 B
    const int smem2 = (2 * 128 * PS) * (int)sizeof(float);         // 135,168 B

    cudaFuncSetAttribute(gat_k1, cudaFuncAttributeMaxDynamicSharedMemorySize, smem1);
    cudaFuncSetAttribute(gat_k2, cudaFuncAttributeMaxDynamicSharedMemorySize, smem2);

    gat_k1<<<128, 256, smem1>>>(h, W, bias, aw);
    gat_k2<<<BB * 16, 256, smem2>>>(adj, out);
}

// round 12
// speedup vs baseline: 1.8857x; 1.1198x over previous
#include <cuda_runtime.h>
#include <string.h>

#define ALPHA 0.2f
#define EPS   1e-5f
#define BB    8
#define NN    2048
#define FF    128
#define PD    258   // k1 dup pitch
#define PS    132   // k1 plain pitch
#define PSP   129   // k2 Pt pitch (odd -> conflict-free phase-A stores; scalar reads ok)
#define PSW   132   // k2 Whs pitch (16B-aligned rows for LDS.128)

typedef unsigned long long ull;
typedef unsigned int uint;

// Scratch (no allocation allowed)
__device__ float g_Wh [BB * NN * FF];
__device__ float g_Wh1[BB * NN];
__device__ float g_Wh2[BB * NN];

__device__ __forceinline__ void fma2(ull& d, ull a, ull b) {
    asm("fma.rn.f32x2 %0, %1, %2, %0;" : "+l"(d) : "l"(a), "l"(b));
}
__device__ __forceinline__ ull splat2(float w) {
    ull d; asm("mov.b64 %0, {%1, %1};" : "=l"(d) : "f"(w)); return d;
}
__device__ __forceinline__ float2 asf2(ull v) { float2 f; memcpy(&f, &v, 8); return f; }
__device__ __forceinline__ ull    asu2(float2 f) { ull v; memcpy(&v, &f, 8); return v; }

// ---------------------------------------------------------------------------
// Kernel 1: Wh = h @ W^T + b ; Wh1 = Wh@a[:128]; Wh2 = Wh@a[128:]  (FFMA2)
// (unchanged from R6 measurement: ~20 us)
// ---------------------------------------------------------------------------
__global__ __launch_bounds__(256) void gat_k1(const float* __restrict__ h,
                                              const float* __restrict__ W,
                                              const float* __restrict__ bias,
                                              const float* __restrict__ aw) {
    extern __shared__ float sm[];
    float* hTd = sm;             // [128 f][PD]
    float* Wt  = sm + 128 * PD;  // [128 f][PS]

    int tid = threadIdx.x;
    int r = tid >> 4, c = tid & 15;
    int row0 = blockIdx.x * 128;

    for (int idx = tid; idx < FF * FF; idx += 256) {
        int o = idx >> 7, f = idx & 127;
        Wt[f * PS + o] = W[idx];
    }
    #pragma unroll
    for (int e = 0; e < 16; e++) {
        int idx = e * 256 + tid;
        int i = idx >> 5, m = idx & 31;
        float4 v = ((const float4*)(h + (size_t)(row0 + i) * FF))[m];
        float2 d;
        d.x = d.y = v.x; *(float2*)(hTd + (4*m+0) * PD + 2*i) = d;
        d.x = d.y = v.y; *(float2*)(hTd + (4*m+1) * PD + 2*i) = d;
        d.x = d.y = v.z; *(float2*)(hTd + (4*m+2) * PD + 2*i) = d;
        d.x = d.y = v.w; *(float2*)(hTd + (4*m+3) * PD + 2*i) = d;
    }
    __syncthreads();

    ull acc[8][4];
    #pragma unroll
    for (int k = 0; k < 4; k++) {
        float2 bp = *(const float2*)(bias + 2*c + 32*k);
        ull bu = asu2(bp);
        #pragma unroll
        for (int u = 0; u < 8; u++) acc[u][k] = bu;
    }

    const float* Bm = Wt + 2 * c;
    #pragma unroll 2
    for (int f = 0; f < 128; f++) {
        ull pv[8], wv[4];
        #pragma unroll
        for (int u = 0; u < 8; u++)
            pv[u] = *(const ull*)(hTd + f * PD + 2 * (r + 16 * u));
        #pragma unroll
        for (int k = 0; k < 4; k++)
            wv[k] = *(const ull*)(Bm + f * PS + 32 * k);
        #pragma unroll
        for (int u = 0; u < 8; u++)
            #pragma unroll
            for (int k = 0; k < 4; k++)
                fma2(acc[u][k], pv[u], wv[k]);
    }

    float2 a1[4], a2[4];
    #pragma unroll
    for (int k = 0; k < 4; k++) {
        a1[k] = *(const float2*)(aw + 2*c + 32*k);
        a2[k] = *(const float2*)(aw + FF + 2*c + 32*k);
    }

    #pragma unroll
    for (int u = 0; u < 8; u++) {
        int row = row0 + r + 16 * u;
        float s1 = 0.f, s2 = 0.f;
        #pragma unroll
        for (int k = 0; k < 4; k++) {
            float2 v = asf2(acc[u][k]);
            *(float2*)(g_Wh + (size_t)row * FF + 2*c + 32*k) = v;
            s1 = fmaf(v.x, a1[k].x, fmaf(v.y, a1[k].y, s1));
            s2 = fmaf(v.x, a2[k].x, fmaf(v.y, a2[k].y, s2));
        }
        #pragma unroll
        for (int d = 1; d < 16; d <<= 1) {
            s1 += __shfl_xor_sync(0xffffffffu, s1, d);
            s2 += __shfl_xor_sync(0xffffffffu, s2, d);
        }
        if (c == 0) { g_Wh1[row] = s1; g_Wh2[row] = s2; }
    }
}

// ---------------------------------------------------------------------------
// Kernel 2 (512 threads = 4 warps/SMSP): fused GAT attention+aggregate+LN+leaky.
// Pt[j][i] pitch 129 (conflict-free scalar stores & broadcast scalar reads).
// Phase B: thread (r=tid/16 in 0..31, c=tid&15): rows {r+32u} u=0..3 (scalar,
// pv splat), col-quads {4c+64k2} via LDS.128 -> natural FFMA2 col-pairs.
// acc[4][4] f32x2 = 32 outputs/thread. 6 LDS + 4 mov + 16 FFMA2 per j.
// ---------------------------------------------------------------------------
__global__ __launch_bounds__(512) void gat_k2(const int* __restrict__ adj,
                                              float* __restrict__ out) {
    extern __shared__ float sm[];
    float* Pt  = sm;              // [128 j][PSP]
    float* Whs = sm + 128 * PSP;  // [128 j][PSW]
    __shared__ float Wh1s[128];
    __shared__ float rs[128];

    int tid  = threadIdx.x;
    int b    = blockIdx.x >> 4;
    int it   = blockIdx.x & 15;
    int r    = tid >> 4, c = tid & 15;     // r 0..31, c 0..15
    int warp = tid >> 5, lane = tid & 31;  // 16 warps

    if (tid < 128) Wh1s[tid] = g_Wh1[b * NN + it * 128 + tid];

    ull acc[4][4];
    #pragma unroll
    for (int u = 0; u < 4; u++)
        #pragma unroll
        for (int k = 0; k < 4; k++) acc[u][k] = 0ULL;
    float rsum[8];
    #pragma unroll
    for (int s = 0; s < 8; s++) rsum[s] = 0.f;

    const size_t adjBase = ((size_t)b * NN + it * 128) * NN;
    __syncthreads();   // Wh1s visible

    for (int jt = 0; jt < 16; jt++) {
        // ---- fill Whs (4096 float4s / 512 threads = 8 iters) ----
        const float4* Whg = (const float4*)(g_Wh + (size_t)(b * NN + jt * 128) * FF);
        #pragma unroll
        for (int e = 0; e < 8; e++) {
            int idx = e * 512 + tid;
            int j = idx >> 5, m = idx & 31;
            float4 v = Whg[idx];
            *(float4*)(Whs + j * PSW + 4 * m) = v;
        }
        float wh2q[4];
        #pragma unroll
        for (int q = 0; q < 4; q++)
            wh2q[q] = g_Wh2[b * NN + jt * 128 + lane + 32 * q];

        // ---- phase A: each warp owns 8 rows; lane covers j = lane+32q ----
        #pragma unroll
        for (int s = 0; s < 8; s++) {
            int li = s * 16 + warp;
            float wh1 = Wh1s[li];
            const int* ap = adj + adjBase + (size_t)li * NN + jt * 128 + lane;
            #pragma unroll
            for (int q = 0; q < 4; q++) {
                int av = ap[32 * q];
                float sc = wh1 + wh2q[q];
                sc = (sc >= 0.f) ? sc : ALPHA * sc;
                float p = av ? __expf(sc) : 0.f;
                rsum[s] += p;
                Pt[(lane + 32 * q) * PSP + li] = p;   // bank = (lane+li)%32: conflict-free
            }
        }
        __syncthreads();

        // ---- phase B ----
        #pragma unroll 2
        for (int j = 0; j < 128; j++) {
            const float* pr = Pt + j * PSP + r;
            ull pd[4];
            #pragma unroll
            for (int u = 0; u < 4; u++) pd[u] = splat2(pr[32 * u]);
            const float* wr = Whs + j * PSW + 4 * c;
            float4 w0 = *(const float4*)(wr);
            float4 w1 = *(const float4*)(wr + 64);
            ull wv[4];
            wv[0] = asu2(make_float2(w0.x, w0.y));
            wv[1] = asu2(make_float2(w0.z, w0.w));
            wv[2] = asu2(make_float2(w1.x, w1.y));
            wv[3] = asu2(make_float2(w1.z, w1.w));
            #pragma unroll
            for (int u = 0; u < 4; u++)
                #pragma unroll
                for (int k = 0; k < 4; k++)
                    fma2(acc[u][k], pd[u], wv[k]);
        }
        __syncthreads();   // reads done before next tile overwrites
    }

    // ---- rowsums: reduce across the 32 lanes of each row's warp ----
    #pragma unroll
    for (int s = 0; s < 8; s++) {
        float v = rsum[s];
        #pragma unroll
        for (int d = 16; d; d >>= 1) v += __shfl_xor_sync(0xffffffffu, v, d);
        if (lane == 0) rs[s * 16 + warp] = v;
    }
    __syncthreads();

    // ---- epilogue: normalize, LayerNorm (reduce over 16 c-lanes), leaky ----
    #pragma unroll
    for (int u = 0; u < 4; u++) {
        int i = r + 32 * u;
        float inv = 1.f / rs[i];
        float2 v[4];
        float s = 0.f, sq = 0.f;
        #pragma unroll
        for (int k = 0; k < 4; k++) {
            float2 a2v = asf2(acc[u][k]);
            v[k].x = a2v.x * inv; v[k].y = a2v.y * inv;
            s += v[k].x + v[k].y;
            sq = fmaf(v[k].x, v[k].x, fmaf(v[k].y, v[k].y, sq));
        }
        #pragma unroll
        for (int d = 1; d < 16; d <<= 1) {
            s  += __shfl_xor_sync(0xffffffffu, s,  d);
            sq += __shfl_xor_sync(0xffffffffu, sq, d);
        }
        float mu   = s * (1.f / 128.f);
        float rstd = rsqrtf(sq * (1.f / 128.f) - mu * mu + EPS);
        float* op = out + (size_t)(b * NN + it * 128 + i) * FF;
        float4 y0, y1;
        y0.x = (v[0].x - mu) * rstd; y0.x = (y0.x >= 0.f) ? y0.x : ALPHA * y0.x;
        y0.y = (v[0].y - mu) * rstd; y0.y = (y0.y >= 0.f) ? y0.y : ALPHA * y0.y;
        y0.z = (v[1].x - mu) * rstd; y0.z = (y0.z >= 0.f) ? y0.z : ALPHA * y0.z;
        y0.w = (v[1].y - mu) * rstd; y0.w = (y0.w >= 0.f) ? y0.w : ALPHA * y0.w;
        y1.x = (v[2].x - mu) * rstd; y1.x = (y1.x >= 0.f) ? y1.x : ALPHA * y1.x;
        y1.y = (v[2].y - mu) * rstd; y1.y = (y1.y >= 0.f) ? y1.y : ALPHA * y1.y;
        y1.z = (v[3].x - mu) * rstd; y1.z = (y1.z >= 0.f) ? y1.z : ALPHA * y1.z;
        y1.w = (v[3].y - mu) * rstd; y1.w = (y1.w >= 0.f) ? y1.w : ALPHA * y1.w;
        *(float4*)(op + 4 * c)      = y0;
        *(float4*)(op + 4 * c + 64) = y1;
    }
}

// ---------------------------------------------------------------------------
extern "C" void kernel_launch(void* const* d_in, const int* in_sizes, int n_in,
                              void* d_out, int out_size) {
    const float* h    = (const float*)d_in[0];
    const int*   adj  = (const int*)  d_in[1];
    const float* W    = (const float*)d_in[2];
    const float* bias = (const float*)d_in[3];
    const float* aw   = (const float*)d_in[4];
    float*       out  = (float*)d_out;

    const int smem1 = (128 * PD + 128 * PS) * (int)sizeof(float);    // 199,680 B
    const int smem2 = (128 * PSP + 128 * PSW) * (int)sizeof(float);  // 133,632 B

    cudaFuncSetAttribute(gat_k1, cudaFuncAttributeMaxDynamicSharedMemorySize, smem1);
    cudaFuncSetAttribute(gat_k2, cudaFuncAttributeMaxDynamicSharedMemorySize, smem2);

    gat_k1<<<128, 256, smem1>>>(h, W, bias, aw);
    gat_k2<<<BB * 16, 512, smem2>>>(adj, out);
}